// round 1
// baseline (speedup 1.0000x reference)
#include <cuda_runtime.h>

#define SEQ 4096
#define HID 1024
#define NCTA 64
#define ROWS_PER_CTA 16
#define EPSF 1e-12f

// Scratch (allocation-free rule: __device__ globals)
__device__ float g_Xn[SEQ * HID];   // normalized embeddings
__device__ float g_P[SEQ * HID];    // W_hi @ x_t + b, precomputed
__device__ int   g_flags[NCTA];     // per-CTA step-completion flags

// ---------------- sync primitives ----------------
__device__ __forceinline__ int ld_acquire(const int* p) {
    int v;
    asm volatile("ld.acquire.gpu.s32 %0, [%1];" : "=r"(v) : "l"(p) : "memory");
    return v;
}
__device__ __forceinline__ void st_release(int* p, int v) {
    asm volatile("st.release.gpu.s32 [%0], %1;" :: "l"(p), "r"(v) : "memory");
}

// ---------------- flag reset (graph-replay safety) ----------------
__global__ void zero_flags_kernel() {
    g_flags[threadIdx.x] = 0;
}

// ---------------- embedding + L2 normalize + out[0]=h0 ----------------
// grid: SEQ blocks x 256 threads; each block handles one token row (1024 f32 = 256 float4)
__global__ __launch_bounds__(256) void embed_kernel(const int* __restrict__ src,
                                                    const float* __restrict__ W,
                                                    const float* __restrict__ h0,
                                                    float* __restrict__ out) {
    const int t   = blockIdx.x;
    const int tid = threadIdx.x;
    const float4* row = reinterpret_cast<const float4*>(W) + (size_t)src[t] * (HID / 4);
    float4 v = row[tid];
    float s = v.x * v.x + v.y * v.y + v.z * v.z + v.w * v.w;
    #pragma unroll
    for (int o = 16; o; o >>= 1) s += __shfl_xor_sync(0xffffffffu, s, o);
    __shared__ float red[8];
    if ((tid & 31) == 0) red[tid >> 5] = s;
    __syncthreads();
    float tot = red[0] + red[1] + red[2] + red[3] + red[4] + red[5] + red[6] + red[7];
    float rn = 1.0f / fmaxf(sqrtf(tot), EPSF);
    float4 o4 = make_float4(v.x * rn, v.y * rn, v.z * rn, v.w * rn);
    reinterpret_cast<float4*>(g_Xn)[(size_t)t * (HID / 4) + tid] = o4;
    if (t == 0) {
        // out[0] = h0
        reinterpret_cast<float4*>(out)[tid] = reinterpret_cast<const float4*>(h0)[tid];
    }
}

// ---------------- GEMM: g_P[m][n] = sum_k g_Xn[m][k] * W_hi[n][k] + b[n] ----------------
#define BM 128
#define BN 64
#define BK 32
__global__ __launch_bounds__(256) void gemm_kernel(const float* __restrict__ Bw,
                                                   const float* __restrict__ bias) {
    __shared__ float As[BK][BM + 4];
    __shared__ float Bs[BK][BN + 4];
    const int tid = threadIdx.x;
    const int m0 = blockIdx.y * BM;
    const int n0 = blockIdx.x * BN;
    const int ty = tid >> 4;   // 0..15 -> 8 rows each
    const int tx = tid & 15;   // 0..15 -> 4 cols each

    float acc[8][4];
    #pragma unroll
    for (int i = 0; i < 8; i++)
        #pragma unroll
        for (int j = 0; j < 4; j++) acc[i][j] = 0.0f;

    for (int k0 = 0; k0 < HID; k0 += BK) {
        // load A tile (128x32) as 1024 float4, transposed into As[k][m]
        #pragma unroll
        for (int i = 0; i < 4; i++) {
            int idx = tid + i * 256;          // 0..1023
            int r = idx >> 3;                  // 0..127
            int kq = idx & 7;                  // 0..7 (float4 within k-chunk)
            float4 f = reinterpret_cast<const float4*>(g_Xn)[(size_t)(m0 + r) * (HID / 4) + (k0 >> 2) + kq];
            As[kq * 4 + 0][r] = f.x;
            As[kq * 4 + 1][r] = f.y;
            As[kq * 4 + 2][r] = f.z;
            As[kq * 4 + 3][r] = f.w;
        }
        // load B tile (64x32) as 512 float4, transposed into Bs[k][n]
        #pragma unroll
        for (int i = 0; i < 2; i++) {
            int idx = tid + i * 256;          // 0..511
            int r = idx >> 3;                  // 0..63
            int kq = idx & 7;
            float4 f = reinterpret_cast<const float4*>(Bw)[(size_t)(n0 + r) * (HID / 4) + (k0 >> 2) + kq];
            Bs[kq * 4 + 0][r] = f.x;
            Bs[kq * 4 + 1][r] = f.y;
            Bs[kq * 4 + 2][r] = f.z;
            Bs[kq * 4 + 3][r] = f.w;
        }
        __syncthreads();
        #pragma unroll
        for (int k = 0; k < BK; k++) {
            float4 a0 = *reinterpret_cast<const float4*>(&As[k][ty * 8]);
            float4 a1 = *reinterpret_cast<const float4*>(&As[k][ty * 8 + 4]);
            float4 b0 = *reinterpret_cast<const float4*>(&Bs[k][tx * 4]);
            float ar[8] = {a0.x, a0.y, a0.z, a0.w, a1.x, a1.y, a1.z, a1.w};
            float br[4] = {b0.x, b0.y, b0.z, b0.w};
            #pragma unroll
            for (int i = 0; i < 8; i++)
                #pragma unroll
                for (int j = 0; j < 4; j++)
                    acc[i][j] = fmaf(ar[i], br[j], acc[i][j]);
        }
        __syncthreads();
    }

    float4 bb = reinterpret_cast<const float4*>(bias)[(n0 >> 2) + tx];
    #pragma unroll
    for (int i = 0; i < 8; i++) {
        int m = m0 + ty * 8 + i;
        float4 o = make_float4(acc[i][0] + bb.x, acc[i][1] + bb.y,
                               acc[i][2] + bb.z, acc[i][3] + bb.w);
        reinterpret_cast<float4*>(g_P)[(size_t)m * (HID / 4) + (n0 >> 2) + tx] = o;
    }
}

// ---------------- persistent sequential RNN ----------------
// 64 CTAs x 512 threads; warp w of CTA c owns row c*16+w; W_hh row in registers.
// step t: read h_{t-1} = out[t], write h_t = out[t+1], then release flag.
__global__ __launch_bounds__(512) void rnn_kernel(const float* __restrict__ Whh,
                                                  float* __restrict__ out) {
    const int warp = threadIdx.x >> 5;
    const int lane = threadIdx.x & 31;
    const int row  = (blockIdx.x << 4) + warp;

    // W_hh row in registers: lane holds elements [4*lane + 128*j .. +3]
    float4 w[8];
    const float4* wr = reinterpret_cast<const float4*>(Whh) + (size_t)row * (HID / 4);
    #pragma unroll
    for (int j = 0; j < 8; j++) w[j] = wr[lane + (j << 5)];

    float pv = g_P[row];  // P[0][row], prefetched

    for (int t = 0; t < SEQ; ++t) {
        if (t > 0) {
            if (warp == 0) {
                for (;;) {
                    int f0 = ld_acquire(&g_flags[lane]);
                    int f1 = ld_acquire(&g_flags[lane + 32]);
                    if (__all_sync(0xffffffffu, (f0 >= t) && (f1 >= t))) break;
                }
            }
            __syncthreads();
        }
        // prefetch next P early (independent of h)
        float pv_next = (t + 1 < SEQ) ? g_P[(size_t)(t + 1) * HID + row] : 0.0f;

        const float4* h4 = reinterpret_cast<const float4*>(out + (size_t)t * HID);
        float s0 = 0.f, s1 = 0.f, s2 = 0.f, s3 = 0.f;
        #pragma unroll
        for (int j = 0; j < 8; j += 4) {
            float4 ha = __ldcg(&h4[lane + ((j + 0) << 5)]);
            float4 hb = __ldcg(&h4[lane + ((j + 1) << 5)]);
            float4 hc = __ldcg(&h4[lane + ((j + 2) << 5)]);
            float4 hd = __ldcg(&h4[lane + ((j + 3) << 5)]);
            s0 = fmaf(w[j + 0].x, ha.x, s0); s0 = fmaf(w[j + 0].y, ha.y, s0);
            s0 = fmaf(w[j + 0].z, ha.z, s0); s0 = fmaf(w[j + 0].w, ha.w, s0);
            s1 = fmaf(w[j + 1].x, hb.x, s1); s1 = fmaf(w[j + 1].y, hb.y, s1);
            s1 = fmaf(w[j + 1].z, hb.z, s1); s1 = fmaf(w[j + 1].w, hb.w, s1);
            s2 = fmaf(w[j + 2].x, hc.x, s2); s2 = fmaf(w[j + 2].y, hc.y, s2);
            s2 = fmaf(w[j + 2].z, hc.z, s2); s2 = fmaf(w[j + 2].w, hc.w, s2);
            s3 = fmaf(w[j + 3].x, hd.x, s3); s3 = fmaf(w[j + 3].y, hd.y, s3);
            s3 = fmaf(w[j + 3].z, hd.z, s3); s3 = fmaf(w[j + 3].w, hd.w, s3);
        }
        float s = (s0 + s1) + (s2 + s3);
        #pragma unroll
        for (int o = 16; o; o >>= 1) s += __shfl_xor_sync(0xffffffffu, s, o);

        float hv = tanhf(s + pv);
        pv = pv_next;
        if (lane == 0) out[(size_t)(t + 1) * HID + row] = hv;
        __syncthreads();
        if (threadIdx.x == 0) st_release(&g_flags[blockIdx.x], t + 1);
    }
}

// ---------------- launch ----------------
extern "C" void kernel_launch(void* const* d_in, const int* in_sizes, int n_in,
                              void* d_out, int out_size) {
    const int*   src  = (const int*)  d_in[0];  // [4096]
    const float* W    = (const float*)d_in[1];  // [32000,1024]
    const float* h0   = (const float*)d_in[2];  // [1024]
    const float* W_hi = (const float*)d_in[3];  // [1024,1024]
    const float* W_hh = (const float*)d_in[4];  // [1024,1024]
    const float* b    = (const float*)d_in[5];  // [1024]
    float* out = (float*)d_out;                 // [4097,1024]

    zero_flags_kernel<<<1, NCTA>>>();
    embed_kernel<<<SEQ, 256>>>(src, W, h0, out);
    gemm_kernel<<<dim3(HID / BN, SEQ / BM), 256>>>(W_hi, b);
    rnn_kernel<<<NCTA, 512>>>(W_hh, out);
}

// round 3
// speedup vs baseline: 1.9270x; 1.9270x over previous
#include <cuda_runtime.h>

#define SEQ 4096
#define HID 1024
#define NCTA 64
#define EPSF 1e-12f

// Scratch (allocation-free rule: __device__ globals)
__device__ float g_Xn[SEQ * HID];              // normalized embeddings
__device__ float g_P[SEQ * HID];               // W_hi @ x_t + b, precomputed
__device__ unsigned long long g_H[2 * HID];    // tagged h double buffer: hi32=tag, lo32=float bits

// ---------------- strong (relaxed-atomic) 8B ld/st: guaranteed visibility ----------------
__device__ __forceinline__ unsigned long long ld_rlx(const unsigned long long* p) {
    unsigned long long v;
    asm volatile("ld.relaxed.gpu.global.u64 %0, [%1];" : "=l"(v) : "l"(p) : "memory");
    return v;
}
__device__ __forceinline__ void st_rlx(unsigned long long* p, unsigned long long v) {
    asm volatile("st.relaxed.gpu.global.u64 [%0], %1;" :: "l"(p), "l"(v) : "memory");
}

// ---------------- init: h0 -> out[0], tagged buf[0] (tag 1), clear buf[1] ----------------
__global__ __launch_bounds__(1024) void init_kernel(const float* __restrict__ h0,
                                                    float* __restrict__ out) {
    int i = threadIdx.x;
    float v = h0[i];
    out[i] = v;
    g_H[i]       = (1ull << 32) | (unsigned long long)__float_as_uint(v);
    g_H[HID + i] = 0ull;
}

// ---------------- embedding + L2 normalize ----------------
__global__ __launch_bounds__(256) void embed_kernel(const int* __restrict__ src,
                                                    const float* __restrict__ W) {
    const int t   = blockIdx.x;
    const int tid = threadIdx.x;
    const float4* row = reinterpret_cast<const float4*>(W) + (size_t)src[t] * (HID / 4);
    float4 v = row[tid];
    float s = v.x * v.x + v.y * v.y + v.z * v.z + v.w * v.w;
    #pragma unroll
    for (int o = 16; o; o >>= 1) s += __shfl_xor_sync(0xffffffffu, s, o);
    __shared__ float red[8];
    if ((tid & 31) == 0) red[tid >> 5] = s;
    __syncthreads();
    float tot = red[0] + red[1] + red[2] + red[3] + red[4] + red[5] + red[6] + red[7];
    float rn = 1.0f / fmaxf(sqrtf(tot), EPSF);
    float4 o4 = make_float4(v.x * rn, v.y * rn, v.z * rn, v.w * rn);
    reinterpret_cast<float4*>(g_Xn)[(size_t)t * (HID / 4) + tid] = o4;
}

// ---------------- GEMM: g_P[m][n] = sum_k g_Xn[m][k] * W_hi[n][k] + b[n] ----------------
#define BM 128
#define BN 64
#define BK 32
__global__ __launch_bounds__(256) void gemm_kernel(const float* __restrict__ Bw,
                                                   const float* __restrict__ bias) {
    __shared__ float As[BK][BM + 4];
    __shared__ float Bs[BK][BN + 4];
    const int tid = threadIdx.x;
    const int m0 = blockIdx.y * BM;
    const int n0 = blockIdx.x * BN;
    const int ty = tid >> 4;
    const int tx = tid & 15;

    float acc[8][4];
    #pragma unroll
    for (int i = 0; i < 8; i++)
        #pragma unroll
        for (int j = 0; j < 4; j++) acc[i][j] = 0.0f;

    for (int k0 = 0; k0 < HID; k0 += BK) {
        #pragma unroll
        for (int i = 0; i < 4; i++) {
            int idx = tid + i * 256;
            int r = idx >> 3;
            int kq = idx & 7;
            float4 f = reinterpret_cast<const float4*>(g_Xn)[(size_t)(m0 + r) * (HID / 4) + (k0 >> 2) + kq];
            As[kq * 4 + 0][r] = f.x;
            As[kq * 4 + 1][r] = f.y;
            As[kq * 4 + 2][r] = f.z;
            As[kq * 4 + 3][r] = f.w;
        }
        #pragma unroll
        for (int i = 0; i < 2; i++) {
            int idx = tid + i * 256;
            int r = idx >> 3;
            int kq = idx & 7;
            float4 f = reinterpret_cast<const float4*>(Bw)[(size_t)(n0 + r) * (HID / 4) + (k0 >> 2) + kq];
            Bs[kq * 4 + 0][r] = f.x;
            Bs[kq * 4 + 1][r] = f.y;
            Bs[kq * 4 + 2][r] = f.z;
            Bs[kq * 4 + 3][r] = f.w;
        }
        __syncthreads();
        #pragma unroll
        for (int k = 0; k < BK; k++) {
            float4 a0 = *reinterpret_cast<const float4*>(&As[k][ty * 8]);
            float4 a1 = *reinterpret_cast<const float4*>(&As[k][ty * 8 + 4]);
            float4 b0 = *reinterpret_cast<const float4*>(&Bs[k][tx * 4]);
            float ar[8] = {a0.x, a0.y, a0.z, a0.w, a1.x, a1.y, a1.z, a1.w};
            float br[4] = {b0.x, b0.y, b0.z, b0.w};
            #pragma unroll
            for (int i = 0; i < 8; i++)
                #pragma unroll
                for (int j = 0; j < 4; j++)
                    acc[i][j] = fmaf(ar[i], br[j], acc[i][j]);
        }
        __syncthreads();
    }

    float4 bb = reinterpret_cast<const float4*>(bias)[(n0 >> 2) + tx];
    #pragma unroll
    for (int i = 0; i < 8; i++) {
        int m = m0 + ty * 8 + i;
        float4 o = make_float4(acc[i][0] + bb.x, acc[i][1] + bb.y,
                               acc[i][2] + bb.z, acc[i][3] + bb.w);
        reinterpret_cast<float4*>(g_P)[(size_t)m * (HID / 4) + (n0 >> 2) + tx] = o;
    }
}

// ---------------- persistent RNN: tagged dataflow + one bar/step ----------------
// 64 CTAs x 8 warps (256 thr). Warp w of CTA c owns rows c*16+2w, c*16+2w+1,
// and stages global tagged chunk [w*128, (w+1)*128) into plain-float smem.
// Sync: value+step-tag packed in one u64, relaxed atomics (strong, guaranteed
// visible); one __syncthreads per step; parity double-buffered smem.
__global__ __launch_bounds__(256) void rnn_kernel(const float* __restrict__ Whh,
                                                  float* __restrict__ out) {
    __shared__ float4 sh[2][HID / 4];            // 8 KB: [parity][h as float4]
    const int warp = threadIdx.x >> 5;
    const int lane = threadIdx.x & 31;
    const int rowA = (blockIdx.x << 4) + (warp << 1);
    const int rowB = rowA + 1;

    // weights for both rows in registers (16 float4 = 64 regs)
    float4 wa[8], wb[8];
    {
        const float4* wra = reinterpret_cast<const float4*>(Whh) + (size_t)rowA * (HID / 4);
        const float4* wrb = wra + (HID / 4);
        #pragma unroll
        for (int j = 0; j < 8; j++) { wa[j] = wra[lane + (j << 5)]; wb[j] = wrb[lane + (j << 5)]; }
    }

    float pa = g_P[rowA], pb = g_P[rowB];
    const int gbase = (warp << 7) + (lane << 2);   // 4 slots per lane

    for (int t = 0; t < SEQ; ++t) {
        const unsigned tag = (unsigned)(t + 1);    // tag of h_t
        const int par = t & 1;

        // prefetch next-step P (independent of h)
        float pan = 0.f, pbn = 0.f;
        if (t + 1 < SEQ) {
            pan = g_P[(size_t)(t + 1) * HID + rowA];
            pbn = g_P[(size_t)(t + 1) * HID + rowB];
        }

        // 1) poll my 4 global tagged slots (relaxed atomics, MLP=4)
        const unsigned long long* gp = g_H + (par << 10) + gbase;
        unsigned long long v0, v1, v2, v3;
        do {
            v0 = ld_rlx(gp + 0);
            v1 = ld_rlx(gp + 1);
            v2 = ld_rlx(gp + 2);
            v3 = ld_rlx(gp + 3);
        } while (((unsigned)(v0 >> 32) != tag) | ((unsigned)(v1 >> 32) != tag) |
                 ((unsigned)(v2 >> 32) != tag) | ((unsigned)(v3 >> 32) != tag));

        // 2) stage plain floats to smem, then one CTA barrier
        sh[par][gbase >> 2] = make_float4(__uint_as_float((unsigned)v0),
                                          __uint_as_float((unsigned)v1),
                                          __uint_as_float((unsigned)v2),
                                          __uint_as_float((unsigned)v3));
        __syncthreads();

        // 3) dual-row dot product from smem (8 conflict-free LDS.128)
        float a0 = 0.f, a1 = 0.f, b0 = 0.f, b1 = 0.f;
        #pragma unroll
        for (int j = 0; j < 8; j++) {
            float4 h = sh[par][lane + (j << 5)];
            a0 = fmaf(wa[j].x, h.x, a0); a1 = fmaf(wa[j].y, h.y, a1);
            a0 = fmaf(wa[j].z, h.z, a0); a1 = fmaf(wa[j].w, h.w, a1);
            b0 = fmaf(wb[j].x, h.x, b0); b1 = fmaf(wb[j].y, h.y, b1);
            b0 = fmaf(wb[j].z, h.z, b0); b1 = fmaf(wb[j].w, h.w, b1);
        }
        float sa = a0 + a1, sb = b0 + b1;
        #pragma unroll
        for (int o = 16; o; o >>= 1) {
            sa += __shfl_xor_sync(0xffffffffu, sa, o);
            sb += __shfl_xor_sync(0xffffffffu, sb, o);
        }

        // 4) one tanh (lane-selected), lanes 0/1 publish
        float s  = (lane == 0) ? (sa + pa) : (sb + pb);
        float hv = tanhf(s);
        pa = pan; pb = pbn;
        if (lane < 2) {
            int r = rowA + lane;
            out[(size_t)(t + 1) * HID + r] = hv;
            unsigned long long wv = ((unsigned long long)(unsigned)(t + 2) << 32)
                                  | (unsigned long long)__float_as_uint(hv);
            st_rlx(g_H + (((t + 1) & 1) << 10) + r, wv);
        }
    }
}

// ---------------- launch ----------------
extern "C" void kernel_launch(void* const* d_in, const int* in_sizes, int n_in,
                              void* d_out, int out_size) {
    const int*   src  = (const int*)  d_in[0];  // [4096]
    const float* W    = (const float*)d_in[1];  // [32000,1024]
    const float* h0   = (const float*)d_in[2];  // [1024]
    const float* W_hi = (const float*)d_in[3];  // [1024,1024]
    const float* W_hh = (const float*)d_in[4];  // [1024,1024]
    const float* b    = (const float*)d_in[5];  // [1024]
    float* out = (float*)d_out;                 // [4097,1024]

    init_kernel<<<1, 1024>>>(h0, out);
    embed_kernel<<<SEQ, 256>>>(src, W);
    gemm_kernel<<<dim3(HID / BN, SEQ / BM), 256>>>(W_hi, b);
    rnn_kernel<<<NCTA, 256>>>(W_hh, out);
}